// round 15
// baseline (speedup 1.0000x reference)
#include <cuda_runtime.h>
#include <cuda_bf16.h>
#include <cstddef>
#include <cstdint>

// Problem constants
#define T_STEPS 256
#define B_SZ    64
#define K_DIM   1024
#define H_DIM   1024
#define L_NUM   3
#define THREE_H 3072
#define M_ROWS  16384
#define NBLK    128
#define NTHR    512

typedef unsigned long long ull;

// ---------------------------------------------------------------------------
// Scratch (device globals — allocation-free per harness rules)
// ---------------------------------------------------------------------------
__device__ float g_gi [(size_t)M_ROWS * THREE_H];   // [T*B, 3H] gate-interleaved
__device__ __nv_bfloat16 g_x16hi[(size_t)M_ROWS * K_DIM];
__device__ __nv_bfloat16 g_x16lo[(size_t)M_ROWS * K_DIM];
__device__ __nv_bfloat16 g_s16hi[(size_t)M_ROWS * K_DIM];
__device__ __nv_bfloat16 g_s16lo[(size_t)M_ROWS * K_DIM];
__device__ __nv_bfloat16 g_w16hi[(size_t)L_NUM * THREE_H * K_DIM];
__device__ __nv_bfloat16 g_w16lo[(size_t)L_NUM * THREE_H * K_DIM];
__device__ uint4 g_hfrag[2][2][8192];               // [pingpong][hi/lo][slots]
// flag-array grid barrier (monotonic, wrap-safe); one cache line per block
__device__ volatile unsigned g_flags[NBLK * 32];
__device__ volatile unsigned g_gen2;

// ---------------------------------------------------------------------------
// helpers
// ---------------------------------------------------------------------------
__device__ __forceinline__ float sigm(float x) { return 1.0f / (1.0f + expf(-x)); }

__device__ __forceinline__ void mma_bf16(
    float* d, uint32_t a0, uint32_t a1, uint32_t a2, uint32_t a3,
    uint32_t b0, uint32_t b1)
{
    asm volatile(
        "mma.sync.aligned.m16n8k16.row.col.f32.bf16.bf16.f32 "
        "{%0,%1,%2,%3}, {%4,%5,%6,%7}, {%8,%9}, {%0,%1,%2,%3};"
        : "+f"(d[0]), "+f"(d[1]), "+f"(d[2]), "+f"(d[3])
        : "r"(a0), "r"(a1), "r"(a2), "r"(a3), "r"(b0), "r"(b1));
}
__device__ __forceinline__ void ldm_x4(uint32_t* r, uint32_t saddr) {
    asm volatile("ldmatrix.sync.aligned.m8n8.x4.shared.b16 {%0,%1,%2,%3}, [%4];"
        : "=r"(r[0]), "=r"(r[1]), "=r"(r[2]), "=r"(r[3]) : "r"(saddr));
}
__device__ __forceinline__ void cp16(void* dst, const void* src) {
    unsigned sa = (unsigned)__cvta_generic_to_shared(dst);
    asm volatile("cp.async.cg.shared.global [%0], [%1], 16;" :: "r"(sa), "l"(src));
}
__device__ __forceinline__ void cp_commit() {
    asm volatile("cp.async.commit_group;" ::: "memory");
}
template <int N>
__device__ __forceinline__ void cp_wait() {
    asm volatile("cp.async.wait_group %0;" :: "n"(N) : "memory");
}

// ---------------------------------------------------------------------------
// Conversion kernels (run once per launch)
// ---------------------------------------------------------------------------
__global__ __launch_bounds__(256) void conv_x_kernel(
    const float* __restrict__ x,
    __nv_bfloat16* __restrict__ hi, __nv_bfloat16* __restrict__ lo)
{
    size_t i = (size_t)blockIdx.x * 256 + threadIdx.x;
    float v = x[i];
    __nv_bfloat16 h = __float2bfloat16(v);
    hi[i] = h;
    lo[i] = __float2bfloat16(v - __bfloat162float(h));
}

__global__ __launch_bounds__(256) void conv_w_kernel(
    const float* __restrict__ wih,
    __nv_bfloat16* __restrict__ hi, __nv_bfloat16* __restrict__ lo)
{
    size_t i = (size_t)blockIdx.x * 256 + threadIdx.x;
    int k   = (int)(i & 1023);
    int r10 = (int)(i >> 10);
    int l   = r10 / THREE_H;
    int n   = r10 - l * THREE_H;
    int row = (n % 3) * H_DIM + n / 3;
    float v = wih[((size_t)l * THREE_H + row) * K_DIM + k];
    __nv_bfloat16 h = __float2bfloat16(v);
    hi[i] = h;
    lo[i] = __float2bfloat16(v - __bfloat162float(h));
}

// ---------------------------------------------------------------------------
// Kernel 1: gi = A @ W^T + bias — bf16 HMMA, 3-term split precision.
// (exact R12 version: BK=64, 1 block/SM, 72-stride smem ldmatrix)
// ---------------------------------------------------------------------------
#define GTILE_B   18432                 // one 128x72 bf16 tile, bytes
#define GSTAGE_B  (4 * GTILE_B)         // Ah, Al, Wh, Wl
#define GI_SMEM   (2 * GSTAGE_B)        // 147456

__global__ __launch_bounds__(256, 1) void gi_gemm_bf16_kernel(
    const __nv_bfloat16* __restrict__ Ahi,
    const __nv_bfloat16* __restrict__ Alo,
    const __nv_bfloat16* __restrict__ Whi,
    const __nv_bfloat16* __restrict__ Wlo,
    const float* __restrict__ bias,
    float* __restrict__ out)
{
    extern __shared__ char gsm[];
    const uint32_t smb = (uint32_t)__cvta_generic_to_shared(gsm);

    const int tid  = threadIdx.x;
    const int w    = tid >> 5;
    const int lane = tid & 31;
    const int wm   = w >> 2;
    const int wn   = w & 3;
    const int bm   = blockIdx.y * 128;
    const int bn   = blockIdx.x * 128;

    const __nv_bfloat16* srcs[4] = {
        Ahi + (size_t)bm * K_DIM, Alo + (size_t)bm * K_DIM,
        Whi + (size_t)bn * K_DIM, Wlo + (size_t)bn * K_DIM
    };

    float bias_v[4][2];
    #pragma unroll
    for (int nt = 0; nt < 4; nt++) {
        int n0 = bn + wn * 32 + nt * 8 + (lane & 3) * 2;
        bias_v[nt][0] = bias[(n0 % 3) * H_DIM + n0 / 3];
        bias_v[nt][1] = bias[((n0 + 1) % 3) * H_DIM + (n0 + 1) / 3];
    }

    float acc[4][4][4];
    #pragma unroll
    for (int mt = 0; mt < 4; mt++)
        #pragma unroll
        for (int nt = 0; nt < 4; nt++)
            #pragma unroll
            for (int r = 0; r < 4; r++)
                acc[mt][nt][r] = 0.0f;

    const uint32_t aRowOff = (uint32_t)((wm * 64 + (lane & 15)) * 144 + (lane >> 4) * 16);
    const uint32_t bRowOff = (uint32_t)((wn * 32 + ((lane >> 4) & 1) * 8 + (lane & 7)) * 144
                                        + ((lane >> 3) & 1) * 16);

    #define GSTAGE(kt, s)                                                      \
    {                                                                          \
        const int k0 = (kt) * 64;                                              \
        _Pragma("unroll")                                                      \
        for (int i = 0; i < 16; i++) {                                         \
            int idx  = i * 256 + tid;                                          \
            int tile = idx >> 10;                                              \
            int r    = (idx >> 3) & 127;                                       \
            int c8   = idx & 7;                                                \
            cp16(gsm + (s) * GSTAGE_B + tile * GTILE_B + r * 144 + c8 * 16,    \
                 srcs[tile] + (size_t)r * K_DIM + k0 + c8 * 8);                \
        }                                                                      \
        cp_commit();                                                           \
    }

    GSTAGE(0, 0);

    for (int kt = 0; kt < 16; kt++) {
        if (kt < 15) {
            GSTAGE(kt + 1, (kt + 1) & 1);
            cp_wait<1>();
        } else {
            cp_wait<0>();
        }
        __syncthreads();

        const uint32_t sb  = smb + (kt & 1) * GSTAGE_B;
        const uint32_t sAh = sb;
        const uint32_t sAl = sb + GTILE_B;
        const uint32_t sWh = sb + 2 * GTILE_B;
        const uint32_t sWl = sb + 3 * GTILE_B;

        #pragma unroll
        for (int k16 = 0; k16 < 4; k16++) {
            uint32_t ah[4][4], al[4][4];
            #pragma unroll
            for (int mt = 0; mt < 4; mt++) {
                uint32_t ao = aRowOff + mt * 16 * 144 + k16 * 32;
                ldm_x4(ah[mt], sAh + ao);
                ldm_x4(al[mt], sAl + ao);
            }
            uint32_t bh[2][4], bl[2][4];
            #pragma unroll
            for (int np = 0; np < 2; np++) {
                uint32_t bo = bRowOff + np * 16 * 144 + k16 * 32;
                ldm_x4(bh[np], sWh + bo);
                ldm_x4(bl[np], sWl + bo);
            }
            #pragma unroll
            for (int mt = 0; mt < 4; mt++)
                #pragma unroll
                for (int nt = 0; nt < 4; nt++) {
                    uint32_t b0h = bh[nt >> 1][(nt & 1) * 2];
                    uint32_t b1h = bh[nt >> 1][(nt & 1) * 2 + 1];
                    uint32_t b0l = bl[nt >> 1][(nt & 1) * 2];
                    uint32_t b1l = bl[nt >> 1][(nt & 1) * 2 + 1];
                    mma_bf16(acc[mt][nt], ah[mt][0], ah[mt][1], ah[mt][2], ah[mt][3], b0h, b1h);
                    mma_bf16(acc[mt][nt], al[mt][0], al[mt][1], al[mt][2], al[mt][3], b0h, b1h);
                    mma_bf16(acc[mt][nt], ah[mt][0], ah[mt][1], ah[mt][2], ah[mt][3], b0l, b1l);
                }
        }
        __syncthreads();
    }
    #undef GSTAGE

    #pragma unroll
    for (int mt = 0; mt < 4; mt++) {
        int m = bm + wm * 64 + mt * 16 + (lane >> 2);
        #pragma unroll
        for (int nt = 0; nt < 4; nt++) {
            int n = bn + wn * 32 + nt * 8 + (lane & 3) * 2;
            float2 v0 = make_float2(acc[mt][nt][0] + bias_v[nt][0],
                                    acc[mt][nt][1] + bias_v[nt][1]);
            float2 v1 = make_float2(acc[mt][nt][2] + bias_v[nt][0],
                                    acc[mt][nt][3] + bias_v[nt][1]);
            *(float2*)(out + (size_t)m * THREE_H + n)       = v0;
            *(float2*)(out + (size_t)(m + 8) * THREE_H + n) = v1;
        }
    }
}

// ---------------------------------------------------------------------------
// Persistent GRU recurrence — mma.sync bf16, fragment-native h layout.
// Flag-array grid barrier: parallel per-block release stores, block 0
// aggregates (127 pollers on distinct lines), monotonic generation release.
// ---------------------------------------------------------------------------
#define WF_BYTES   98304                    // 3 nt * 64 kstep * 32 lanes * 16B
#define RED_B      WF_BYTES
#define RDYN_BYTES (WF_BYTES + 16 * 32 * 12 * 4)   // + 24576 = 122880

__device__ __forceinline__ void grid_sync_(unsigned target) {
    __threadfence();
    __syncthreads();
    const int tid = threadIdx.x;
    if (blockIdx.x == 0) {
        if (tid > 0 && tid < NBLK) {
            while ((int)(g_flags[tid * 32] - target) < 0) { }
        }
        __syncthreads();
        if (tid == 0) {
            __threadfence();
            g_gen2 = target;
        }
    } else {
        if (tid == 0) {
            g_flags[blockIdx.x * 32] = target;
            while ((int)(g_gen2 - target) < 0) __nanosleep(20);
        }
    }
    __threadfence();
    __syncthreads();
}

// fragment address (bf16 units) of element (row b, col k) in a frag buffer
__device__ __forceinline__ int frag_addr_bf16(int b, int k) {
    int mt  = b >> 4, rr = b & 15;
    int ks  = k >> 4, c16 = k & 15;
    int rg  = (rr >> 3) | ((c16 >> 3) << 1);
    int ln  = (rr & 7) * 4 + ((c16 & 7) >> 1);
    int u32 = (mt * 64 + ks) * 128 + ln * 4 + rg;
    return u32 * 2 + (c16 & 1);
}

__global__ __launch_bounds__(NTHR, 1) void gru_persistent_kernel(
    const float* __restrict__ gi,     // [T, B, 3H] interleaved
    const float* __restrict__ whh,    // [3H, H]
    const float* __restrict__ bhh,    // [3H]
    const float* __restrict__ h0l,    // [B, H] this layer's h0
    __nv_bfloat16* __restrict__ s16hi, // [T*B, H] or nullptr
    __nv_bfloat16* __restrict__ s16lo,
    float* __restrict__ hlast)        // [B, H]
{
    extern __shared__ char dynb[];
    uint4* Wf  = (uint4*)dynb;                 // [3 nt][64 kstep][32] frag slots
    float* red = (float*)(dynb + RED_B);       // [16 w][32 lane][12]

    const int tid   = threadIdx.x;
    const int w     = tid >> 5;
    const int lane  = tid & 31;
    const int jbase = blockIdx.x * 8;

    // base generation for this launch (stable: no block can advance g_gen2
    // until every block has passed its own first barrier)
    const unsigned gen0 = g_gen2;

    // ---- convert Whh slice -> bf16 hi/lo fragment smem (once) ----
    {
        __nv_bfloat16* Wb = (__nv_bfloat16*)Wf;
        for (int idx = tid; idx < 24576; idx += NTHR) {
            int c = idx >> 10, k = idx & 1023;
            int row = (c % 3) * H_DIM + (jbase + c / 3);
            float wv = whh[(size_t)row * H_DIM + k];
            __nv_bfloat16 hi = __float2bfloat16(wv);
            __nv_bfloat16 lo = __float2bfloat16(wv - __bfloat162float(hi));
            int nt = c >> 3, n8 = c & 7;
            int ks = k >> 4, c16 = k & 15;
            int ln = n8 * 4 + ((c16 & 7) >> 1);
            int br2 = c16 >> 3;
            int hf = c16 & 1;
            size_t o = ((size_t)(nt * 64 + ks) * 32 + ln) * 8 + br2 * 2 + hf;
            Wb[o]     = hi;
            Wb[o + 4] = lo;
        }
    }

    // ---- init global h fragment buffer 0 (each block: disjoint slice) ----
    {
        int idx = blockIdx.x * NTHR + tid;     // 128*512 = 65536 exactly
        int b = idx >> 10, k = idx & 1023;
        float v = h0l[b * H_DIM + k];
        __nv_bfloat16 hi = __float2bfloat16(v);
        int fa = frag_addr_bf16(b, k);
        ((__nv_bfloat16*)g_hfrag[0][0])[fa] = hi;
        ((__nv_bfloat16*)g_hfrag[0][1])[fa] =
            __float2bfloat16(v - __bfloat162float(hi));
    }

    // mainloop constants
    const int mtile = w & 3;
    const int kslab = w >> 2;
    const int aoff  = (mtile * 64 + kslab * 16) * 32 + lane;   // uint4 idx

    // epilogue constants
    const int ep_b  = tid >> 3;
    const int ep_j  = tid & 7;
    const int ep_jg = jbase + ep_j;
    const float br  = bhh[ep_jg];
    const float bz  = bhh[H_DIM + ep_jg];
    const float bn_ = bhh[2 * H_DIM + ep_jg];
    const int ep_fa = frag_addr_bf16(ep_b, ep_jg);
    float hp_reg = h0l[ep_b * H_DIM + ep_jg];

    __syncthreads();

    const bool wr_seq = (s16hi != nullptr);

    for (int t = 0; t < T_STEPS; t++) {
        const uint4* Ahi = g_hfrag[t & 1][0] + aoff;
        const uint4* Alo = g_hfrag[t & 1][1] + aoff;
        __nv_bfloat16* hiOut = (__nv_bfloat16*)g_hfrag[(t + 1) & 1][0] + ep_fa;
        __nv_bfloat16* loOut = (__nv_bfloat16*)g_hfrag[(t + 1) & 1][1] + ep_fa;
        const float* gi_t = gi + (size_t)t * B_SZ * THREE_H;

        // prefetch gi (static data, independent of barrier — overlaps spin)
        float ga = __ldg(gi_t + (size_t)ep_b * THREE_H + ep_jg * 3 + 0);
        float gb = __ldg(gi_t + (size_t)ep_b * THREE_H + ep_jg * 3 + 1);
        float gc = __ldg(gi_t + (size_t)ep_b * THREE_H + ep_jg * 3 + 2);

        grid_sync_(gen0 + (unsigned)t + 1u);   // prev-step h visible

        float acc[3][4];
        #pragma unroll
        for (int nt = 0; nt < 3; nt++)
            #pragma unroll
            for (int r = 0; r < 4; r++)
                acc[nt][r] = 0.0f;

        #pragma unroll
        for (int k = 0; k < 16; k++) {
            uint4 ah = __ldcg(Ahi + k * 32);
            uint4 al = __ldcg(Alo + k * 32);
            const int kg = kslab * 16 + k;
            #pragma unroll
            for (int nt = 0; nt < 3; nt++) {
                uint4 bv = Wf[(nt * 64 + kg) * 32 + lane];
                mma_bf16(acc[nt], ah.x, ah.y, ah.z, ah.w, bv.x, bv.y);
                mma_bf16(acc[nt], al.x, al.y, al.z, al.w, bv.x, bv.y);
                mma_bf16(acc[nt], ah.x, ah.y, ah.z, ah.w, bv.z, bv.w);
            }
        }

        __syncthreads();
        {
            float* mine = red + (w * 32 + lane) * 12;
            #pragma unroll
            for (int nt = 0; nt < 3; nt++)
                #pragma unroll
                for (int r = 0; r < 4; r++)
                    mine[nt * 4 + r] = acc[nt][r];
        }
        __syncthreads();

        {
            const int m  = ep_b >> 4;
            const int bl = ep_b & 15;
            float s[3];
            #pragma unroll
            for (int g = 0; g < 3; g++) {
                int c   = ep_j * 3 + g;
                int nt  = c >> 3;
                int cr  = c & 7;
                int ln  = (bl & 7) * 4 + (cr >> 1);
                int rg  = ((bl >> 3) << 1) + (cr & 1);
                int idx = nt * 4 + rg;
                float acc_s = 0.f;
                #pragma unroll
                for (int ks = 0; ks < 4; ks++)
                    acc_s += red[((ks * 4 + m) * 32 + ln) * 12 + idx];
                s[g] = acc_s;
            }
            float r  = sigm(ga + s[0] + br);
            float z  = sigm(gb + s[1] + bz);
            float n  = tanhf(gc + r * (s[2] + bn_));
            float hn = (1.0f - z) * n + z * hp_reg;
            hp_reg = hn;
            __nv_bfloat16 hi = __float2bfloat16(hn);
            __nv_bfloat16 lo = __float2bfloat16(hn - __bfloat162float(hi));
            *hiOut = hi;
            *loOut = lo;
            if (wr_seq) {
                size_t so = ((size_t)t * B_SZ + ep_b) * H_DIM + ep_jg;
                s16hi[so] = hi;
                s16lo[so] = lo;
            }
            if (t == T_STEPS - 1)
                hlast[(size_t)ep_b * H_DIM + ep_jg] = hn;
        }
        // no trailing __syncthreads: next step's grid_sync_ orders red reuse
    }
}

// ---------------------------------------------------------------------------
// Launch: conversions once, then per layer — bf16 gi GEMM + recurrence.
// ---------------------------------------------------------------------------
extern "C" void kernel_launch(void* const* d_in, const int* in_sizes, int n_in,
                              void* d_out, int out_size)
{
    (void)in_sizes; (void)n_in; (void)out_size;

    const float* x    = (const float*)d_in[0];
    const float* h0   = (const float*)d_in[1];
    const float* w_ih = (const float*)d_in[2];
    const float* w_hh = (const float*)d_in[3];
    const float* b_ih = (const float*)d_in[4];
    const float* b_hh = (const float*)d_in[5];
    float* out = (float*)d_out;

    float* gi = nullptr;
    __nv_bfloat16 *xhi = nullptr, *xlo = nullptr, *shi = nullptr, *slo = nullptr;
    __nv_bfloat16 *whi = nullptr, *wlo = nullptr;
    cudaGetSymbolAddress((void**)&gi,  g_gi);
    cudaGetSymbolAddress((void**)&xhi, g_x16hi);
    cudaGetSymbolAddress((void**)&xlo, g_x16lo);
    cudaGetSymbolAddress((void**)&shi, g_s16hi);
    cudaGetSymbolAddress((void**)&slo, g_s16lo);
    cudaGetSymbolAddress((void**)&whi, g_w16hi);
    cudaGetSymbolAddress((void**)&wlo, g_w16lo);

    cudaFuncSetAttribute(gru_persistent_kernel,
                         cudaFuncAttributeMaxDynamicSharedMemorySize,
                         RDYN_BYTES);
    cudaFuncSetAttribute(gi_gemm_bf16_kernel,
                         cudaFuncAttributeMaxDynamicSharedMemorySize,
                         GI_SMEM);

    conv_x_kernel<<<65536, 256>>>(x, xhi, xlo);
    conv_w_kernel<<<36864, 256>>>(w_ih, whi, wlo);

    const size_t BH = (size_t)B_SZ * H_DIM;   // 65536
    dim3 ggrid(THREE_H / 128, M_ROWS / 128);  // (24, 128)

    for (int l = 0; l < L_NUM; l++) {
        const __nv_bfloat16* Ahi = (l == 0) ? xhi : shi;
        const __nv_bfloat16* Alo = (l == 0) ? xlo : slo;
        gi_gemm_bf16_kernel<<<ggrid, 256, GI_SMEM>>>(
            Ahi, Alo,
            whi + (size_t)l * THREE_H * K_DIM,
            wlo + (size_t)l * THREE_H * K_DIM,
            b_ih + (size_t)l * THREE_H,
            gi);
        gru_persistent_kernel<<<NBLK, NTHR, RDYN_BYTES>>>(
            gi,
            w_hh + (size_t)l * THREE_H * K_DIM,
            b_hh + (size_t)l * THREE_H,
            h0 + (size_t)l * BH,
            (l < L_NUM - 1) ? shi : nullptr,
            (l < L_NUM - 1) ? slo : nullptr,
            out + (size_t)l * BH);
    }
}

// round 16
// speedup vs baseline: 1.0860x; 1.0860x over previous
#include <cuda_runtime.h>
#include <cuda_bf16.h>
#include <cstddef>
#include <cstdint>

// Problem constants
#define T_STEPS 256
#define B_SZ    64
#define K_DIM   1024
#define H_DIM   1024
#define L_NUM   3
#define THREE_H 3072
#define M_ROWS  16384
#define NBLK    128
#define NTHR    512

typedef unsigned long long ull;

// ---------------------------------------------------------------------------
// Scratch (device globals — allocation-free per harness rules)
// ---------------------------------------------------------------------------
__device__ float g_gi [(size_t)M_ROWS * THREE_H];   // [T*B, 3H] gate-interleaved
__device__ __nv_bfloat16 g_x16hi[(size_t)M_ROWS * K_DIM];
__device__ __nv_bfloat16 g_x16lo[(size_t)M_ROWS * K_DIM];
__device__ __nv_bfloat16 g_s16hi[(size_t)M_ROWS * K_DIM];
__device__ __nv_bfloat16 g_s16lo[(size_t)M_ROWS * K_DIM];
__device__ __nv_bfloat16 g_w16hi[(size_t)L_NUM * THREE_H * K_DIM];
__device__ __nv_bfloat16 g_w16lo[(size_t)L_NUM * THREE_H * K_DIM];
__device__ uint4 g_hfrag[2][2][8192];               // [pingpong][hi/lo][slots]
// flat grid barrier (proven fastest: R12)
__device__ unsigned g_bar_cnt = 0;
__device__ unsigned g_bar_gen = 0;

// ---------------------------------------------------------------------------
// helpers
// ---------------------------------------------------------------------------
__device__ __forceinline__ float sigm(float x) { return 1.0f / (1.0f + expf(-x)); }

__device__ __forceinline__ void mma_bf16(
    float* d, uint32_t a0, uint32_t a1, uint32_t a2, uint32_t a3,
    uint32_t b0, uint32_t b1)
{
    asm volatile(
        "mma.sync.aligned.m16n8k16.row.col.f32.bf16.bf16.f32 "
        "{%0,%1,%2,%3}, {%4,%5,%6,%7}, {%8,%9}, {%0,%1,%2,%3};"
        : "+f"(d[0]), "+f"(d[1]), "+f"(d[2]), "+f"(d[3])
        : "r"(a0), "r"(a1), "r"(a2), "r"(a3), "r"(b0), "r"(b1));
}
__device__ __forceinline__ void ldm_x4(uint32_t* r, uint32_t saddr) {
    asm volatile("ldmatrix.sync.aligned.m8n8.x4.shared.b16 {%0,%1,%2,%3}, [%4];"
        : "=r"(r[0]), "=r"(r[1]), "=r"(r[2]), "=r"(r[3]) : "r"(saddr));
}
__device__ __forceinline__ void cp16(void* dst, const void* src) {
    unsigned sa = (unsigned)__cvta_generic_to_shared(dst);
    asm volatile("cp.async.cg.shared.global [%0], [%1], 16;" :: "r"(sa), "l"(src));
}
__device__ __forceinline__ void cp_commit() {
    asm volatile("cp.async.commit_group;" ::: "memory");
}
template <int N>
__device__ __forceinline__ void cp_wait() {
    asm volatile("cp.async.wait_group %0;" :: "n"(N) : "memory");
}

// ---------------------------------------------------------------------------
// Conversion kernels (run once per launch)
// ---------------------------------------------------------------------------
__global__ __launch_bounds__(256) void conv_x_kernel(
    const float* __restrict__ x,
    __nv_bfloat16* __restrict__ hi, __nv_bfloat16* __restrict__ lo)
{
    size_t i = (size_t)blockIdx.x * 256 + threadIdx.x;
    float v = x[i];
    __nv_bfloat16 h = __float2bfloat16(v);
    hi[i] = h;
    lo[i] = __float2bfloat16(v - __bfloat162float(h));
}

__global__ __launch_bounds__(256) void conv_w_kernel(
    const float* __restrict__ wih,
    __nv_bfloat16* __restrict__ hi, __nv_bfloat16* __restrict__ lo)
{
    size_t i = (size_t)blockIdx.x * 256 + threadIdx.x;
    int k   = (int)(i & 1023);
    int r10 = (int)(i >> 10);
    int l   = r10 / THREE_H;
    int n   = r10 - l * THREE_H;
    int row = (n % 3) * H_DIM + n / 3;
    float v = wih[((size_t)l * THREE_H + row) * K_DIM + k];
    __nv_bfloat16 h = __float2bfloat16(v);
    hi[i] = h;
    lo[i] = __float2bfloat16(v - __bfloat162float(h));
}

// ---------------------------------------------------------------------------
// Kernel 1: gi = A @ W^T + bias — bf16 HMMA, 3-term split precision.
// (exact R12 version: BK=64, 1 block/SM, 72-stride smem ldmatrix)
// ---------------------------------------------------------------------------
#define GTILE_B   18432                 // one 128x72 bf16 tile, bytes
#define GSTAGE_B  (4 * GTILE_B)         // Ah, Al, Wh, Wl
#define GI_SMEM   (2 * GSTAGE_B)        // 147456

__global__ __launch_bounds__(256, 1) void gi_gemm_bf16_kernel(
    const __nv_bfloat16* __restrict__ Ahi,
    const __nv_bfloat16* __restrict__ Alo,
    const __nv_bfloat16* __restrict__ Whi,
    const __nv_bfloat16* __restrict__ Wlo,
    const float* __restrict__ bias,
    float* __restrict__ out)
{
    extern __shared__ char gsm[];
    const uint32_t smb = (uint32_t)__cvta_generic_to_shared(gsm);

    const int tid  = threadIdx.x;
    const int w    = tid >> 5;
    const int lane = tid & 31;
    const int wm   = w >> 2;
    const int wn   = w & 3;
    const int bm   = blockIdx.y * 128;
    const int bn   = blockIdx.x * 128;

    const __nv_bfloat16* srcs[4] = {
        Ahi + (size_t)bm * K_DIM, Alo + (size_t)bm * K_DIM,
        Whi + (size_t)bn * K_DIM, Wlo + (size_t)bn * K_DIM
    };

    float bias_v[4][2];
    #pragma unroll
    for (int nt = 0; nt < 4; nt++) {
        int n0 = bn + wn * 32 + nt * 8 + (lane & 3) * 2;
        bias_v[nt][0] = bias[(n0 % 3) * H_DIM + n0 / 3];
        bias_v[nt][1] = bias[((n0 + 1) % 3) * H_DIM + (n0 + 1) / 3];
    }

    float acc[4][4][4];
    #pragma unroll
    for (int mt = 0; mt < 4; mt++)
        #pragma unroll
        for (int nt = 0; nt < 4; nt++)
            #pragma unroll
            for (int r = 0; r < 4; r++)
                acc[mt][nt][r] = 0.0f;

    const uint32_t aRowOff = (uint32_t)((wm * 64 + (lane & 15)) * 144 + (lane >> 4) * 16);
    const uint32_t bRowOff = (uint32_t)((wn * 32 + ((lane >> 4) & 1) * 8 + (lane & 7)) * 144
                                        + ((lane >> 3) & 1) * 16);

    #define GSTAGE(kt, s)                                                      \
    {                                                                          \
        const int k0 = (kt) * 64;                                              \
        _Pragma("unroll")                                                      \
        for (int i = 0; i < 16; i++) {                                         \
            int idx  = i * 256 + tid;                                          \
            int tile = idx >> 10;                                              \
            int r    = (idx >> 3) & 127;                                       \
            int c8   = idx & 7;                                                \
            cp16(gsm + (s) * GSTAGE_B + tile * GTILE_B + r * 144 + c8 * 16,    \
                 srcs[tile] + (size_t)r * K_DIM + k0 + c8 * 8);                \
        }                                                                      \
        cp_commit();                                                           \
    }

    GSTAGE(0, 0);

    for (int kt = 0; kt < 16; kt++) {
        if (kt < 15) {
            GSTAGE(kt + 1, (kt + 1) & 1);
            cp_wait<1>();
        } else {
            cp_wait<0>();
        }
        __syncthreads();

        const uint32_t sb  = smb + (kt & 1) * GSTAGE_B;
        const uint32_t sAh = sb;
        const uint32_t sAl = sb + GTILE_B;
        const uint32_t sWh = sb + 2 * GTILE_B;
        const uint32_t sWl = sb + 3 * GTILE_B;

        #pragma unroll
        for (int k16 = 0; k16 < 4; k16++) {
            uint32_t ah[4][4], al[4][4];
            #pragma unroll
            for (int mt = 0; mt < 4; mt++) {
                uint32_t ao = aRowOff + mt * 16 * 144 + k16 * 32;
                ldm_x4(ah[mt], sAh + ao);
                ldm_x4(al[mt], sAl + ao);
            }
            uint32_t bh[2][4], bl[2][4];
            #pragma unroll
            for (int np = 0; np < 2; np++) {
                uint32_t bo = bRowOff + np * 16 * 144 + k16 * 32;
                ldm_x4(bh[np], sWh + bo);
                ldm_x4(bl[np], sWl + bo);
            }
            #pragma unroll
            for (int mt = 0; mt < 4; mt++)
                #pragma unroll
                for (int nt = 0; nt < 4; nt++) {
                    uint32_t b0h = bh[nt >> 1][(nt & 1) * 2];
                    uint32_t b1h = bh[nt >> 1][(nt & 1) * 2 + 1];
                    uint32_t b0l = bl[nt >> 1][(nt & 1) * 2];
                    uint32_t b1l = bl[nt >> 1][(nt & 1) * 2 + 1];
                    mma_bf16(acc[mt][nt], ah[mt][0], ah[mt][1], ah[mt][2], ah[mt][3], b0h, b1h);
                    mma_bf16(acc[mt][nt], al[mt][0], al[mt][1], al[mt][2], al[mt][3], b0h, b1h);
                    mma_bf16(acc[mt][nt], ah[mt][0], ah[mt][1], ah[mt][2], ah[mt][3], b0l, b1l);
                }
        }
        __syncthreads();
    }
    #undef GSTAGE

    #pragma unroll
    for (int mt = 0; mt < 4; mt++) {
        int m = bm + wm * 64 + mt * 16 + (lane >> 2);
        #pragma unroll
        for (int nt = 0; nt < 4; nt++) {
            int n = bn + wn * 32 + nt * 8 + (lane & 3) * 2;
            float2 v0 = make_float2(acc[mt][nt][0] + bias_v[nt][0],
                                    acc[mt][nt][1] + bias_v[nt][1]);
            float2 v1 = make_float2(acc[mt][nt][2] + bias_v[nt][0],
                                    acc[mt][nt][3] + bias_v[nt][1]);
            *(float2*)(out + (size_t)m * THREE_H + n)       = v0;
            *(float2*)(out + (size_t)(m + 8) * THREE_H + n) = v1;
        }
    }
}

// ---------------------------------------------------------------------------
// Persistent GRU recurrence — mma.sync bf16, fragment-native h layout.
// Flat atomic grid barrier (R12-proven). gi operands prefetched before the
// barrier; no trailing per-step __syncthreads (barrier's sync orders red).
// ---------------------------------------------------------------------------
#define WF_BYTES   98304                    // 3 nt * 64 kstep * 32 lanes * 16B
#define RED_B      WF_BYTES
#define RDYN_BYTES (WF_BYTES + 16 * 32 * 12 * 4)   // + 24576 = 122880

__device__ __forceinline__ void grid_sync_() {
    __threadfence();
    __syncthreads();
    if (threadIdx.x == 0) {
        unsigned gen = *(volatile unsigned*)&g_bar_gen;
        unsigned ticket = atomicAdd(&g_bar_cnt, 1u);
        if (ticket == NBLK - 1) {
            g_bar_cnt = 0;
            __threadfence();
            atomicAdd(&g_bar_gen, 1u);
        } else {
            while (*(volatile unsigned*)&g_bar_gen == gen) __nanosleep(20);
        }
    }
    __syncthreads();
}

// fragment address (bf16 units) of element (row b, col k) in a frag buffer
__device__ __forceinline__ int frag_addr_bf16(int b, int k) {
    int mt  = b >> 4, rr = b & 15;
    int ks  = k >> 4, c16 = k & 15;
    int rg  = (rr >> 3) | ((c16 >> 3) << 1);
    int ln  = (rr & 7) * 4 + ((c16 & 7) >> 1);
    int u32 = (mt * 64 + ks) * 128 + ln * 4 + rg;
    return u32 * 2 + (c16 & 1);
}

__global__ __launch_bounds__(NTHR, 1) void gru_persistent_kernel(
    const float* __restrict__ gi,     // [T, B, 3H] interleaved
    const float* __restrict__ whh,    // [3H, H]
    const float* __restrict__ bhh,    // [3H]
    const float* __restrict__ h0l,    // [B, H] this layer's h0
    __nv_bfloat16* __restrict__ s16hi, // [T*B, H] or nullptr
    __nv_bfloat16* __restrict__ s16lo,
    float* __restrict__ hlast)        // [B, H]
{
    extern __shared__ char dynb[];
    uint4* Wf  = (uint4*)dynb;                 // [3 nt][64 kstep][32] frag slots
    float* red = (float*)(dynb + RED_B);       // [16 w][32 lane][12]

    const int tid   = threadIdx.x;
    const int w     = tid >> 5;
    const int lane  = tid & 31;
    const int jbase = blockIdx.x * 8;

    // ---- convert Whh slice -> bf16 hi/lo fragment smem (once) ----
    {
        __nv_bfloat16* Wb = (__nv_bfloat16*)Wf;
        for (int idx = tid; idx < 24576; idx += NTHR) {
            int c = idx >> 10, k = idx & 1023;
            int row = (c % 3) * H_DIM + (jbase + c / 3);
            float wv = whh[(size_t)row * H_DIM + k];
            __nv_bfloat16 hi = __float2bfloat16(wv);
            __nv_bfloat16 lo = __float2bfloat16(wv - __bfloat162float(hi));
            int nt = c >> 3, n8 = c & 7;
            int ks = k >> 4, c16 = k & 15;
            int ln = n8 * 4 + ((c16 & 7) >> 1);
            int br2 = c16 >> 3;
            int hf = c16 & 1;
            size_t o = ((size_t)(nt * 64 + ks) * 32 + ln) * 8 + br2 * 2 + hf;
            Wb[o]     = hi;
            Wb[o + 4] = lo;
        }
    }

    // ---- init global h fragment buffer 0 (each block: disjoint slice) ----
    {
        int idx = blockIdx.x * NTHR + tid;     // 128*512 = 65536 exactly
        int b = idx >> 10, k = idx & 1023;
        float v = h0l[b * H_DIM + k];
        __nv_bfloat16 hi = __float2bfloat16(v);
        int fa = frag_addr_bf16(b, k);
        ((__nv_bfloat16*)g_hfrag[0][0])[fa] = hi;
        ((__nv_bfloat16*)g_hfrag[0][1])[fa] =
            __float2bfloat16(v - __bfloat162float(hi));
    }

    // mainloop constants
    const int mtile = w & 3;
    const int kslab = w >> 2;
    const int aoff  = (mtile * 64 + kslab * 16) * 32 + lane;   // uint4 idx

    // epilogue constants
    const int ep_b  = tid >> 3;
    const int ep_j  = tid & 7;
    const int ep_jg = jbase + ep_j;
    const float br  = bhh[ep_jg];
    const float bz  = bhh[H_DIM + ep_jg];
    const float bn_ = bhh[2 * H_DIM + ep_jg];
    const int ep_fa = frag_addr_bf16(ep_b, ep_jg);
    float hp_reg = h0l[ep_b * H_DIM + ep_jg];

    __syncthreads();

    const bool wr_seq = (s16hi != nullptr);

    for (int t = 0; t < T_STEPS; t++) {
        const uint4* Ahi = g_hfrag[t & 1][0] + aoff;
        const uint4* Alo = g_hfrag[t & 1][1] + aoff;
        __nv_bfloat16* hiOut = (__nv_bfloat16*)g_hfrag[(t + 1) & 1][0] + ep_fa;
        __nv_bfloat16* loOut = (__nv_bfloat16*)g_hfrag[(t + 1) & 1][1] + ep_fa;
        const float* gi_t = gi + (size_t)t * B_SZ * THREE_H;

        // prefetch gi (static data, independent of barrier — overlaps spin)
        float ga = __ldg(gi_t + (size_t)ep_b * THREE_H + ep_jg * 3 + 0);
        float gb = __ldg(gi_t + (size_t)ep_b * THREE_H + ep_jg * 3 + 1);
        float gc = __ldg(gi_t + (size_t)ep_b * THREE_H + ep_jg * 3 + 2);

        grid_sync_();   // prev-step h fragments visible everywhere

        float acc[3][4];
        #pragma unroll
        for (int nt = 0; nt < 3; nt++)
            #pragma unroll
            for (int r = 0; r < 4; r++)
                acc[nt][r] = 0.0f;

        #pragma unroll
        for (int k = 0; k < 16; k++) {
            uint4 ah = __ldcg(Ahi + k * 32);
            uint4 al = __ldcg(Alo + k * 32);
            const int kg = kslab * 16 + k;
            #pragma unroll
            for (int nt = 0; nt < 3; nt++) {
                uint4 bv = Wf[(nt * 64 + kg) * 32 + lane];
                mma_bf16(acc[nt], ah.x, ah.y, ah.z, ah.w, bv.x, bv.y);
                mma_bf16(acc[nt], al.x, al.y, al.z, al.w, bv.x, bv.y);
                mma_bf16(acc[nt], ah.x, ah.y, ah.z, ah.w, bv.z, bv.w);
            }
        }

        __syncthreads();
        {
            float* mine = red + (w * 32 + lane) * 12;
            #pragma unroll
            for (int nt = 0; nt < 3; nt++)
                #pragma unroll
                for (int r = 0; r < 4; r++)
                    mine[nt * 4 + r] = acc[nt][r];
        }
        __syncthreads();

        {
            const int m  = ep_b >> 4;
            const int bl = ep_b & 15;
            float s[3];
            #pragma unroll
            for (int g = 0; g < 3; g++) {
                int c   = ep_j * 3 + g;
                int nt  = c >> 3;
                int cr  = c & 7;
                int ln  = (bl & 7) * 4 + (cr >> 1);
                int rg  = ((bl >> 3) << 1) + (cr & 1);
                int idx = nt * 4 + rg;
                float acc_s = 0.f;
                #pragma unroll
                for (int ks = 0; ks < 4; ks++)
                    acc_s += red[((ks * 4 + m) * 32 + ln) * 12 + idx];
                s[g] = acc_s;
            }
            float r  = sigm(ga + s[0] + br);
            float z  = sigm(gb + s[1] + bz);
            float n  = tanhf(gc + r * (s[2] + bn_));
            float hn = (1.0f - z) * n + z * hp_reg;
            hp_reg = hn;
            __nv_bfloat16 hi = __float2bfloat16(hn);
            __nv_bfloat16 lo = __float2bfloat16(hn - __bfloat162float(hi));
            *hiOut = hi;
            *loOut = lo;
            if (wr_seq) {
                size_t so = ((size_t)t * B_SZ + ep_b) * H_DIM + ep_jg;
                s16hi[so] = hi;
                s16lo[so] = lo;
            }
            if (t == T_STEPS - 1)
                hlast[(size_t)ep_b * H_DIM + ep_jg] = hn;
        }
        // no trailing __syncthreads: next step's grid_sync_ orders red reuse
    }
}

// ---------------------------------------------------------------------------
// Launch: conversions once, then per layer — bf16 gi GEMM + recurrence.
// ---------------------------------------------------------------------------
extern "C" void kernel_launch(void* const* d_in, const int* in_sizes, int n_in,
                              void* d_out, int out_size)
{
    (void)in_sizes; (void)n_in; (void)out_size;

    const float* x    = (const float*)d_in[0];
    const float* h0   = (const float*)d_in[1];
    const float* w_ih = (const float*)d_in[2];
    const float* w_hh = (const float*)d_in[3];
    const float* b_ih = (const float*)d_in[4];
    const float* b_hh = (const float*)d_in[5];
    float* out = (float*)d_out;

    float* gi = nullptr;
    __nv_bfloat16 *xhi = nullptr, *xlo = nullptr, *shi = nullptr, *slo = nullptr;
    __nv_bfloat16 *whi = nullptr, *wlo = nullptr;
    cudaGetSymbolAddress((void**)&gi,  g_gi);
    cudaGetSymbolAddress((void**)&xhi, g_x16hi);
    cudaGetSymbolAddress((void**)&xlo, g_x16lo);
    cudaGetSymbolAddress((void**)&shi, g_s16hi);
    cudaGetSymbolAddress((void**)&slo, g_s16lo);
    cudaGetSymbolAddress((void**)&whi, g_w16hi);
    cudaGetSymbolAddress((void**)&wlo, g_w16lo);

    cudaFuncSetAttribute(gru_persistent_kernel,
                         cudaFuncAttributeMaxDynamicSharedMemorySize,
                         RDYN_BYTES);
    cudaFuncSetAttribute(gi_gemm_bf16_kernel,
                         cudaFuncAttributeMaxDynamicSharedMemorySize,
                         GI_SMEM);

    conv_x_kernel<<<65536, 256>>>(x, xhi, xlo);
    conv_w_kernel<<<36864, 256>>>(w_ih, whi, wlo);

    const size_t BH = (size_t)B_SZ * H_DIM;   // 65536
    dim3 ggrid(THREE_H / 128, M_ROWS / 128);  // (24, 128)

    for (int l = 0; l < L_NUM; l++) {
        const __nv_bfloat16* Ahi = (l == 0) ? xhi : shi;
        const __nv_bfloat16* Alo = (l == 0) ? xlo : slo;
        gi_gemm_bf16_kernel<<<ggrid, 256, GI_SMEM>>>(
            Ahi, Alo,
            whi + (size_t)l * THREE_H * K_DIM,
            wlo + (size_t)l * THREE_H * K_DIM,
            b_ih + (size_t)l * THREE_H,
            gi);
        gru_persistent_kernel<<<NBLK, NTHR, RDYN_BYTES>>>(
            gi,
            w_hh + (size_t)l * THREE_H * H_DIM,
            b_hh + (size_t)l * THREE_H,
            h0 + (size_t)l * BH,
            (l < L_NUM - 1) ? shi : nullptr,
            (l < L_NUM - 1) ? slo : nullptr,
            out + (size_t)l * BH);
    }
}